// round 5
// baseline (speedup 1.0000x reference)
#include <cuda_runtime.h>
#include <cuda_bf16.h>
#include <cstdint>

// ============================================================================
// GraphSAGE fused layer — sm_103 baseline-PTX version (no tcgen05: harness
// compiles for plain sm_103, so arch-specific 'a' instructions are rejected).
//
//   out = relu(concat(feature[nodes], mean(feature[neigh_idx],1)) @ W)
//   B=50000 (from in_sizes), S=10, D=128, H=128, K=2D=256.
//
// Design:
//   * persistent kernel, grid = 148 CTAs x 256 threads
//   * weights pre-transposed ([N][K] K-major), hi/lo bf16 split, written to
//     __device__ scratch by a small prep kernel; each CTA copies them to smem
//     ONCE (weight L2 traffic 19 MB instead of 100 MB)
//   * per 64-row tile: warp-per-row gather + fp32 mean (L2-resident feature
//     table), fp32 -> bf16 hi/lo split into smem A tiles
//   * GEMM: mma.sync.m16n8k16 bf16, 3 products (Ah*Wh + Al*Wh + Ah*Wl) for
//     ~2^-16 effective precision; ldmatrix with 528B row pitch (conflict-free)
//   * ReLU epilogue straight from accumulators to gmem
// ============================================================================

static constexpr int BLK_M   = 64;
static constexpr int K_DIM   = 256;
static constexpr int H_OUT   = 128;
static constexpr int S_NEIGH = 10;
static constexpr int ROW_ELEM = 264;                 // 256 + 8 pad (bf16)
static constexpr int ROW_B    = ROW_ELEM * 2;        // 528 bytes
static constexpr int W_BYTES  = H_OUT * ROW_B;       // 67584
static constexpr int A_BYTES  = BLK_M * ROW_B;       // 33792

// smem layout
static constexpr int SM_WHI = 0;
static constexpr int SM_WLO = SM_WHI + W_BYTES;
static constexpr int SM_AHI = SM_WLO + W_BYTES;      // 135168
static constexpr int SM_ALO = SM_AHI + A_BYTES;      // 168960
static constexpr int SM_TOTAL = SM_ALO + A_BYTES;    // 202752 (< 227 KB)

// pre-split, pre-transposed weight scratch
__device__ __align__(16) unsigned char g_whi[W_BYTES];
__device__ __align__(16) unsigned char g_wlo[W_BYTES];

__device__ __forceinline__ uint32_t smem_u32(const void* p) {
    uint32_t a;
    asm("{ .reg .u64 t; cvta.to.shared.u64 t, %1; cvt.u32.u64 %0, t; }"
        : "=r"(a) : "l"(p));
    return a;
}

__device__ __forceinline__ void split_bf16(float x, __nv_bfloat16& h, __nv_bfloat16& l) {
    h = __float2bfloat16(x);
    l = __float2bfloat16(x - __bfloat162float(h));
}

__device__ __forceinline__ void ldsm_x4(uint32_t (&d)[4], uint32_t addr) {
    asm volatile("ldmatrix.sync.aligned.m8n8.x4.shared.b16 {%0,%1,%2,%3}, [%4];"
                 : "=r"(d[0]), "=r"(d[1]), "=r"(d[2]), "=r"(d[3]) : "r"(addr));
}

__device__ __forceinline__ void mma_bf16(float (&c)[4], const uint32_t (&a)[4],
                                         uint32_t b0, uint32_t b1) {
    asm volatile(
        "mma.sync.aligned.m16n8k16.row.col.f32.bf16.bf16.f32 "
        "{%0,%1,%2,%3}, {%4,%5,%6,%7}, {%8,%9}, {%0,%1,%2,%3};"
        : "+f"(c[0]), "+f"(c[1]), "+f"(c[2]), "+f"(c[3])
        : "r"(a[0]), "r"(a[1]), "r"(a[2]), "r"(a[3]), "r"(b0), "r"(b1));
}

// ---------------- weight prep: transpose + hi/lo split into scratch ----------
__global__ void sage_prep_weight(const float* __restrict__ w) {
    int i = blockIdx.x * blockDim.x + threadIdx.x;   // over K_DIM*H_OUT
    if (i >= K_DIM * H_OUT) return;
    int k = i >> 7;        // weight row   (0..255)
    int n = i & 127;       // weight col   (0..127)
    __nv_bfloat16 h, l;
    split_bf16(w[i], h, l);
    uint32_t off = (uint32_t)n * ROW_B + (uint32_t)k * 2;   // B tile [n][k] K-major
    *reinterpret_cast<__nv_bfloat16*>(g_whi + off) = h;
    *reinterpret_cast<__nv_bfloat16*>(g_wlo + off) = l;
}

// ---------------- fused persistent kernel ------------------------------------
__global__ __launch_bounds__(256, 1)
void sage_main(const int* __restrict__ nodes,
               const int* __restrict__ neigh,
               const float* __restrict__ feat,
               float* __restrict__ out,
               int B, int ntiles) {
    extern __shared__ __align__(16) char smem[];
    const uint32_t sb   = smem_u32(smem);
    const int tid  = threadIdx.x;
    const int wid  = tid >> 5;
    const int lane = tid & 31;

    // --- copy both weight halves into smem once ---
    {
        const uint4* s0 = reinterpret_cast<const uint4*>(g_whi);
        const uint4* s1 = reinterpret_cast<const uint4*>(g_wlo);
        uint4* d0 = reinterpret_cast<uint4*>(smem + SM_WHI);
        uint4* d1 = reinterpret_cast<uint4*>(smem + SM_WLO);
        for (int i = tid; i < W_BYTES / 16; i += 256) { d0[i] = s0[i]; d1[i] = s1[i]; }
    }

    const float4* feat4 = reinterpret_cast<const float4*>(feat);

    // warp tile: 32 rows x 32 cols; warp grid 2 x 4 over the 64x128 CTA tile
    const int mr = (wid & 1) * 32;
    const int nc = (wid >> 1) * 32;

    const uint32_t sAhi = sb + SM_AHI;
    const uint32_t sAlo = sb + SM_ALO;
    const uint32_t sWhi = sb + SM_WHI;
    const uint32_t sWlo = sb + SM_WLO;

    for (int tile = blockIdx.x; tile < ntiles; tile += gridDim.x) {
        const int base = tile * BLK_M;

        __syncthreads();   // prev GEMM done reading A (and W copy on iter 0)

        // ---------- gather + mean + bf16 split into A tiles ----------
        #pragma unroll 1
        for (int i = 0; i < BLK_M / 8; i++) {
            const int r = wid * 8 + i;
            const int grow = base + r;
            const int src = (grow < B) ? grow : 0;

            const int self_idx = __ldg(nodes + src);
            const float4 sv = __ldg(feat4 + (size_t)self_idx * 32 + lane);

            float ax = 0.f, ay = 0.f, az = 0.f, aw = 0.f;
            const int* nrow = neigh + (size_t)src * S_NEIGH;
            #pragma unroll
            for (int s = 0; s < S_NEIGH; s++) {
                const int ni = __ldg(nrow + s);
                const float4 v = __ldg(feat4 + (size_t)ni * 32 + lane);
                ax += v.x; ay += v.y; az += v.z; aw += v.w;
            }
            const float inv = 0.1f;
            const float4 mv = make_float4(ax * inv, ay * inv, az * inv, aw * inv);

            #pragma unroll
            for (int part = 0; part < 2; part++) {
                const float4 v = part ? mv : sv;
                const int kcol = part * 128 + 4 * lane;
                __nv_bfloat16 h0,h1,h2,h3,l0,l1,l2,l3;
                split_bf16(v.x, h0, l0); split_bf16(v.y, h1, l1);
                split_bf16(v.z, h2, l2); split_bf16(v.w, h3, l3);
                __nv_bfloat162 hp0{h0,h1}, hp1{h2,h3}, lp0{l0,l1}, lp1{l2,l3};
                uint2 hp, lp;
                hp.x = *reinterpret_cast<uint32_t*>(&hp0);
                hp.y = *reinterpret_cast<uint32_t*>(&hp1);
                lp.x = *reinterpret_cast<uint32_t*>(&lp0);
                lp.y = *reinterpret_cast<uint32_t*>(&lp1);
                const uint32_t off = (uint32_t)r * ROW_B + (uint32_t)kcol * 2;
                *reinterpret_cast<uint2*>(smem + SM_AHI + off) = hp;
                *reinterpret_cast<uint2*>(smem + SM_ALO + off) = lp;
            }
        }

        __syncthreads();   // A visible to all warps

        // ---------- GEMM: acc = Ah*Wh + Al*Wh + Ah*Wl ----------
        float acc[2][4][4];
        #pragma unroll
        for (int m = 0; m < 2; m++)
            #pragma unroll
            for (int n = 0; n < 4; n++)
                #pragma unroll
                for (int j = 0; j < 4; j++) acc[m][n][j] = 0.f;

        // ldmatrix address components (constant across k except column)
        const uint32_t a_row  = (uint32_t)(mr + (lane & 15));
        const uint32_t a_coff = (uint32_t)(((lane >> 4) << 3) * 2);
        const uint32_t b_row  = (uint32_t)(nc + (lane & 7) + ((lane & 16) >> 1));
        const uint32_t b_coff = (uint32_t)((lane & 8) * 2);

        #pragma unroll
        for (int k = 0; k < K_DIM / 16; k++) {
            const uint32_t kb = (uint32_t)(k * 32);   // 16 bf16 = 32 bytes
            const uint32_t aoff = a_row * ROW_B + a_coff + kb;
            const uint32_t boff = b_row * ROW_B + b_coff + kb;

            uint32_t ah0[4], ah1[4], al0[4], al1[4];
            ldsm_x4(ah0, sAhi + aoff);
            ldsm_x4(ah1, sAhi + aoff + 16 * ROW_B);
            ldsm_x4(al0, sAlo + aoff);
            ldsm_x4(al1, sAlo + aoff + 16 * ROW_B);

            uint32_t bh0[4], bh1[4], bl0[4], bl1[4];
            ldsm_x4(bh0, sWhi + boff);
            ldsm_x4(bh1, sWhi + boff + 16 * ROW_B);
            ldsm_x4(bl0, sWlo + boff);
            ldsm_x4(bl1, sWlo + boff + 16 * ROW_B);

            // n-tiles: 0:{bh0[0],bh0[1]} 1:{bh0[2],bh0[3]} 2:{bh1[0],bh1[1]} 3:{bh1[2],bh1[3]}
            mma_bf16(acc[0][0], ah0, bh0[0], bh0[1]);
            mma_bf16(acc[0][1], ah0, bh0[2], bh0[3]);
            mma_bf16(acc[0][2], ah0, bh1[0], bh1[1]);
            mma_bf16(acc[0][3], ah0, bh1[2], bh1[3]);
            mma_bf16(acc[1][0], ah1, bh0[0], bh0[1]);
            mma_bf16(acc[1][1], ah1, bh0[2], bh0[3]);
            mma_bf16(acc[1][2], ah1, bh1[0], bh1[1]);
            mma_bf16(acc[1][3], ah1, bh1[2], bh1[3]);

            mma_bf16(acc[0][0], al0, bh0[0], bh0[1]);
            mma_bf16(acc[0][1], al0, bh0[2], bh0[3]);
            mma_bf16(acc[0][2], al0, bh1[0], bh1[1]);
            mma_bf16(acc[0][3], al0, bh1[2], bh1[3]);
            mma_bf16(acc[1][0], al1, bh0[0], bh0[1]);
            mma_bf16(acc[1][1], al1, bh0[2], bh0[3]);
            mma_bf16(acc[1][2], al1, bh1[0], bh1[1]);
            mma_bf16(acc[1][3], al1, bh1[2], bh1[3]);

            mma_bf16(acc[0][0], ah0, bl0[0], bl0[1]);
            mma_bf16(acc[0][1], ah0, bl0[2], bl0[3]);
            mma_bf16(acc[0][2], ah0, bl1[0], bl1[1]);
            mma_bf16(acc[0][3], ah0, bl1[2], bl1[3]);
            mma_bf16(acc[1][0], ah1, bl0[0], bl0[1]);
            mma_bf16(acc[1][1], ah1, bl0[2], bl0[3]);
            mma_bf16(acc[1][2], ah1, bl1[0], bl1[1]);
            mma_bf16(acc[1][3], ah1, bl1[2], bl1[3]);
        }

        // ---------- ReLU epilogue ----------
        #pragma unroll
        for (int mi = 0; mi < 2; mi++) {
            const int r0 = base + mr + mi * 16 + (lane >> 2);
            #pragma unroll
            for (int nt = 0; nt < 4; nt++) {
                const int c = nc + nt * 8 + 2 * (lane & 3);
                if (r0 < B) {
                    float2 v;
                    v.x = fmaxf(acc[mi][nt][0], 0.f);
                    v.y = fmaxf(acc[mi][nt][1], 0.f);
                    *reinterpret_cast<float2*>(out + (size_t)r0 * H_OUT + c) = v;
                }
                if (r0 + 8 < B) {
                    float2 v;
                    v.x = fmaxf(acc[mi][nt][2], 0.f);
                    v.y = fmaxf(acc[mi][nt][3], 0.f);
                    *reinterpret_cast<float2*>(out + (size_t)(r0 + 8) * H_OUT + c) = v;
                }
            }
        }
    }
}

// ---------------- launch ------------------------------------------------------
extern "C" void kernel_launch(void* const* d_in, const int* in_sizes, int n_in,
                              void* d_out, int out_size) {
    const int*   nodes  = (const int*)d_in[0];
    const int*   neigh  = (const int*)d_in[1];
    const float* feat   = (const float*)d_in[2];
    const float* weight = (const float*)d_in[3];
    float*       out    = (float*)d_out;
    const int B = in_sizes[0];
    const int ntiles = (B + BLK_M - 1) / BLK_M;

    sage_prep_weight<<<(K_DIM * H_OUT + 255) / 256, 256>>>(weight);

    cudaFuncSetAttribute(sage_main, cudaFuncAttributeMaxDynamicSharedMemorySize, SM_TOTAL);
    const int grid = (ntiles < 148) ? ntiles : 148;
    sage_main<<<grid, 256, SM_TOTAL>>>(nodes, neigh, feat, out, B, ntiles);
}

// round 6
// speedup vs baseline: 1.4325x; 1.4325x over previous
#include <cuda_runtime.h>
#include <cuda_bf16.h>
#include <cstdint>

// ============================================================================
// GraphSAGE fused layer — sm_103 baseline-PTX, warp-specialized pipeline.
//
//   out = relu(concat(feature[nodes], mean(feature[neigh_idx],1)) @ W)
//   B=50000, S=10, D=128, H=128, K=256.
//
// R5 design (from R4 ncu: issue 12.7%, occ 12.4%, nothing saturated =>
// latency-bound; gather and GEMM phases serialized):
//   * 512 threads: warps 0-7 = PRODUCERS (gather + mean + bf16 hi/lo split),
//     warps 8-15 = CONSUMERS (mma.sync bf16 x3 products + ReLU epilogue)
//   * BLK_M=32 tile, 2-stage A ring in smem, mbarrier full/empty handshake
//     => tile time ~ max(gather, gemm) instead of sum, 16 warps resident
//   * weights pre-split/pre-transposed into __device__ scratch, copied to
//     smem once per CTA (persistent kernel, grid=148)
// ============================================================================

static constexpr int BLK_M   = 32;
static constexpr int K_DIM   = 256;
static constexpr int H_OUT   = 128;
static constexpr int S_NEIGH = 10;
static constexpr int ROW_ELEM = 264;                  // 256 + 8 pad (bf16)
static constexpr int ROW_B    = ROW_ELEM * 2;         // 528 bytes
static constexpr int W_BYTES  = H_OUT * ROW_B;        // 67584 per half
static constexpr int A_HALF   = BLK_M * ROW_B;        // 16896 (hi or lo)
static constexpr int A_STAGE  = 2 * A_HALF;           // 33792 (hi+lo)
static constexpr int NSTAGE   = 2;

// smem layout
static constexpr int SM_WHI   = 0;
static constexpr int SM_WLO   = SM_WHI + W_BYTES;     // 67584
static constexpr int SM_A     = SM_WLO + W_BYTES;     // 135168
static constexpr int SM_BAR   = SM_A + NSTAGE * A_STAGE;  // 202752
static constexpr int SM_TOTAL = SM_BAR + 64;          // 202816

// pre-split, pre-transposed weight scratch
__device__ __align__(16) unsigned char g_whi[W_BYTES];
__device__ __align__(16) unsigned char g_wlo[W_BYTES];

// ---------------- helpers ----------------
__device__ __forceinline__ uint32_t smem_u32(const void* p) {
    uint32_t a;
    asm("{ .reg .u64 t; cvta.to.shared.u64 t, %1; cvt.u32.u64 %0, t; }"
        : "=r"(a) : "l"(p));
    return a;
}

__device__ __forceinline__ void split_bf16(float x, __nv_bfloat16& h, __nv_bfloat16& l) {
    h = __float2bfloat16(x);
    l = __float2bfloat16(x - __bfloat162float(h));
}

__device__ __forceinline__ void ldsm_x4(uint32_t (&d)[4], uint32_t addr) {
    asm volatile("ldmatrix.sync.aligned.m8n8.x4.shared.b16 {%0,%1,%2,%3}, [%4];"
                 : "=r"(d[0]), "=r"(d[1]), "=r"(d[2]), "=r"(d[3]) : "r"(addr));
}

__device__ __forceinline__ void mma_bf16(float (&c)[4], const uint32_t (&a)[4],
                                         uint32_t b0, uint32_t b1) {
    asm volatile(
        "mma.sync.aligned.m16n8k16.row.col.f32.bf16.bf16.f32 "
        "{%0,%1,%2,%3}, {%4,%5,%6,%7}, {%8,%9}, {%0,%1,%2,%3};"
        : "+f"(c[0]), "+f"(c[1]), "+f"(c[2]), "+f"(c[3])
        : "r"(a[0]), "r"(a[1]), "r"(a[2]), "r"(a[3]), "r"(b0), "r"(b1));
}

#define MBARRIER_INIT(mbar, count) \
    asm volatile("mbarrier.init.shared.b64 [%0], %1;" \
                 :: "r"((uint32_t)(mbar)), "r"((uint32_t)(count)) : "memory")

#define MBARRIER_ARRIVE(mbar) \
    asm volatile("mbarrier.arrive.shared.b64 _, [%0];" \
                 :: "r"((uint32_t)(mbar)) : "memory")

#define MBARRIER_WAIT_PARITY(mbar, parity) do {                                  \
    uint32_t _m = (uint32_t)(mbar); uint32_t _p = (uint32_t)(parity);            \
    asm volatile(                                                                \
        "{\n\t.reg .pred P1;\n\t"                                                \
        "WAIT_LOOP_%=:\n\t"                                                      \
        "mbarrier.try_wait.parity.shared.b64 P1, [%0], %1;\n\t"                  \
        "@P1 bra.uni WAIT_DONE_%=;\n\t"                                          \
        "bra.uni WAIT_LOOP_%=;\n\t"                                              \
        "WAIT_DONE_%=:\n\t}"                                                     \
        :: "r"(_m), "r"(_p) : "memory");                                         \
} while (0)

#define FULL_BAR(sb, s)  ((sb) + SM_BAR + (s) * 16)
#define EMPTY_BAR(sb, s) ((sb) + SM_BAR + (s) * 16 + 8)

// ---------------- weight prep: transpose + hi/lo split into scratch ----------
__global__ void sage_prep_weight(const float* __restrict__ w) {
    int i = blockIdx.x * blockDim.x + threadIdx.x;
    if (i >= K_DIM * H_OUT) return;
    int k = i >> 7;        // weight row (0..255)
    int n = i & 127;       // weight col (0..127)
    __nv_bfloat16 h, l;
    split_bf16(w[i], h, l);
    uint32_t off = (uint32_t)n * ROW_B + (uint32_t)k * 2;   // [n][k] K-major
    *reinterpret_cast<__nv_bfloat16*>(g_whi + off) = h;
    *reinterpret_cast<__nv_bfloat16*>(g_wlo + off) = l;
}

// ---------------- fused persistent warp-specialized kernel -------------------
__global__ __launch_bounds__(512, 1)
void sage_main(const int* __restrict__ nodes,
               const int* __restrict__ neigh,
               const float* __restrict__ feat,
               float* __restrict__ out,
               int B, int ntiles) {
    extern __shared__ __align__(16) char smem[];
    const uint32_t sb   = smem_u32(smem);
    const int tid  = threadIdx.x;
    const int wid  = tid >> 5;
    const int lane = tid & 31;

    if (tid == 0) {
        #pragma unroll
        for (int s = 0; s < NSTAGE; s++) {
            MBARRIER_INIT(FULL_BAR(sb, s), 256);   // producer threads arrive
            MBARRIER_INIT(EMPTY_BAR(sb, s), 256);  // consumer threads arrive
        }
    }

    // copy both weight halves into smem once
    {
        const uint4* s0 = reinterpret_cast<const uint4*>(g_whi);
        const uint4* s1 = reinterpret_cast<const uint4*>(g_wlo);
        uint4* d0 = reinterpret_cast<uint4*>(smem + SM_WHI);
        uint4* d1 = reinterpret_cast<uint4*>(smem + SM_WLO);
        for (int i = tid; i < W_BYTES / 16; i += 512) { d0[i] = s0[i]; d1[i] = s1[i]; }
    }
    __syncthreads();

    if (wid < 8) {
        // ============ PRODUCERS: gather + mean + bf16 split ============
        const float4* feat4 = reinterpret_cast<const float4*>(feat);
        int stage = 0, phase = 1;   // first empty-wait passes immediately

        for (int tile = blockIdx.x; tile < ntiles; tile += gridDim.x) {
            const int base = tile * BLK_M;
            MBARRIER_WAIT_PARITY(EMPTY_BAR(sb, stage), phase);
            const uint32_t aHi = sb + SM_A + stage * A_STAGE;
            const uint32_t aLo = aHi + A_HALF;

            #pragma unroll 2
            for (int i = 0; i < 4; i++) {
                const int r = wid * 4 + i;                 // 0..31
                const int grow = base + r;
                const int src = (grow < B) ? grow : 0;

                const int self_idx = __ldg(nodes + src);
                const float4 sv = __ldg(feat4 + (size_t)self_idx * 32 + lane);

                float ax = 0.f, ay = 0.f, az = 0.f, aw = 0.f;
                const int* nrow = neigh + (size_t)src * S_NEIGH;
                #pragma unroll
                for (int s = 0; s < S_NEIGH; s++) {
                    const int ni = __ldg(nrow + s);
                    const float4 v = __ldg(feat4 + (size_t)ni * 32 + lane);
                    ax += v.x; ay += v.y; az += v.z; aw += v.w;
                }
                const float4 mv = make_float4(ax * 0.1f, ay * 0.1f, az * 0.1f, aw * 0.1f);

                #pragma unroll
                for (int part = 0; part < 2; part++) {
                    const float4 v = part ? mv : sv;
                    const int kcol = part * 128 + 4 * lane;
                    __nv_bfloat16 h0,h1,h2,h3,l0,l1,l2,l3;
                    split_bf16(v.x, h0, l0); split_bf16(v.y, h1, l1);
                    split_bf16(v.z, h2, l2); split_bf16(v.w, h3, l3);
                    __nv_bfloat162 hp0{h0,h1}, hp1{h2,h3}, lp0{l0,l1}, lp1{l2,l3};
                    const uint32_t hx = *reinterpret_cast<uint32_t*>(&hp0);
                    const uint32_t hy = *reinterpret_cast<uint32_t*>(&hp1);
                    const uint32_t lx = *reinterpret_cast<uint32_t*>(&lp0);
                    const uint32_t ly = *reinterpret_cast<uint32_t*>(&lp1);
                    const uint32_t off = (uint32_t)r * ROW_B + (uint32_t)kcol * 2;
                    asm volatile("st.shared.v2.b32 [%0], {%1, %2};"
                                 :: "r"(aHi + off), "r"(hx), "r"(hy) : "memory");
                    asm volatile("st.shared.v2.b32 [%0], {%1, %2};"
                                 :: "r"(aLo + off), "r"(lx), "r"(ly) : "memory");
                }
            }

            __threadfence_block();
            MBARRIER_ARRIVE(FULL_BAR(sb, stage));
            if (++stage == NSTAGE) { stage = 0; phase ^= 1; }
        }
    } else {
        // ============ CONSUMERS: GEMM (3 bf16 products) + ReLU ============
        const int cw = wid - 8;                       // 0..7
        const int mr = (cw & 1) * 16;                 // 0 or 16
        const int nc = (cw >> 1) * 32;                // 0,32,64,96
        const uint32_t sWhi = sb + SM_WHI;
        const uint32_t sWlo = sb + SM_WLO;

        const uint32_t a_row  = (uint32_t)(mr + (lane & 15));
        const uint32_t a_coff = (uint32_t)(((lane >> 4) << 3) * 2);
        const uint32_t b_row  = (uint32_t)(nc + (lane & 7) + ((lane & 16) >> 1));
        const uint32_t b_coff = (uint32_t)((lane & 8) * 2);
        const uint32_t aoff0  = a_row * ROW_B + a_coff;
        const uint32_t boff0  = b_row * ROW_B + b_coff;

        int stage = 0, phase = 0;

        for (int tile = blockIdx.x; tile < ntiles; tile += gridDim.x) {
            const int base = tile * BLK_M;
            MBARRIER_WAIT_PARITY(FULL_BAR(sb, stage), phase);
            const uint32_t aHi = sb + SM_A + stage * A_STAGE;
            const uint32_t aLo = aHi + A_HALF;

            float acc[4][4];
            #pragma unroll
            for (int n = 0; n < 4; n++)
                #pragma unroll
                for (int j = 0; j < 4; j++) acc[n][j] = 0.f;

            #pragma unroll
            for (int k = 0; k < K_DIM / 16; k++) {
                const uint32_t kb = (uint32_t)(k * 32);

                uint32_t ah[4], al[4];
                ldsm_x4(ah, aHi + aoff0 + kb);
                ldsm_x4(al, aLo + aoff0 + kb);

                uint32_t bh0[4], bh1[4], bl0[4], bl1[4];
                ldsm_x4(bh0, sWhi + boff0 + kb);
                ldsm_x4(bh1, sWhi + boff0 + kb + 16 * ROW_B);
                ldsm_x4(bl0, sWlo + boff0 + kb);
                ldsm_x4(bl1, sWlo + boff0 + kb + 16 * ROW_B);

                mma_bf16(acc[0], ah, bh0[0], bh0[1]);
                mma_bf16(acc[1], ah, bh0[2], bh0[3]);
                mma_bf16(acc[2], ah, bh1[0], bh1[1]);
                mma_bf16(acc[3], ah, bh1[2], bh1[3]);

                mma_bf16(acc[0], al, bh0[0], bh0[1]);
                mma_bf16(acc[1], al, bh0[2], bh0[3]);
                mma_bf16(acc[2], al, bh1[0], bh1[1]);
                mma_bf16(acc[3], al, bh1[2], bh1[3]);

                mma_bf16(acc[0], ah, bl0[0], bl0[1]);
                mma_bf16(acc[1], ah, bl0[2], bl0[3]);
                mma_bf16(acc[2], ah, bl1[0], bl1[1]);
                mma_bf16(acc[3], ah, bl1[2], bl1[3]);
            }

            MBARRIER_ARRIVE(EMPTY_BAR(sb, stage));
            if (++stage == NSTAGE) { stage = 0; phase ^= 1; }

            // epilogue from registers (after releasing the stage)
            const int r0 = base + mr + (lane >> 2);
            #pragma unroll
            for (int nt = 0; nt < 4; nt++) {
                const int c = nc + nt * 8 + 2 * (lane & 3);
                if (r0 < B) {
                    float2 v;
                    v.x = fmaxf(acc[nt][0], 0.f);
                    v.y = fmaxf(acc[nt][1], 0.f);
                    *reinterpret_cast<float2*>(out + (size_t)r0 * H_OUT + c) = v;
                }
                if (r0 + 8 < B) {
                    float2 v;
                    v.x = fmaxf(acc[nt][2], 0.f);
                    v.y = fmaxf(acc[nt][3], 0.f);
                    *reinterpret_cast<float2*>(out + (size_t)(r0 + 8) * H_OUT + c) = v;
                }
            }
        }
    }
}

// ---------------- launch ------------------------------------------------------
extern "C" void kernel_launch(void* const* d_in, const int* in_sizes, int n_in,
                              void* d_out, int out_size) {
    const int*   nodes  = (const int*)d_in[0];
    const int*   neigh  = (const int*)d_in[1];
    const float* feat   = (const float*)d_in[2];
    const float* weight = (const float*)d_in[3];
    float*       out    = (float*)d_out;
    const int B = in_sizes[0];
    const int ntiles = (B + BLK_M - 1) / BLK_M;

    sage_prep_weight<<<(K_DIM * H_OUT + 255) / 256, 256>>>(weight);

    cudaFuncSetAttribute(sage_main, cudaFuncAttributeMaxDynamicSharedMemorySize, SM_TOTAL);
    const int grid = (ntiles < 148) ? ntiles : 148;
    sage_main<<<grid, 512, SM_TOTAL>>>(nodes, neigh, feat, out, B, ntiles);
}

// round 7
// speedup vs baseline: 1.5392x; 1.0745x over previous
#include <cuda_runtime.h>
#include <cuda_bf16.h>
#include <cstdint>

// ============================================================================
// GraphSAGE fused layer — sm_103 baseline-PTX, warp-specialized pipeline (R6).
//
//   out = relu(concat(feature[nodes], mean(feature[neigh_idx],1)) @ W)
//   B=50000, S=10, D=128, H=128, K=256.
//
// R6 deltas vs R5 (from ncu: L1 57.4% dominated by LDSM; latency-exposed):
//   * consumers: two groups of 4 warps; group g consumes stage g (even/odd
//     tiles). Each warp does a 32x32 tile => A-frags amortized over 2x rows,
//     LDSM x4-ops per tile 768 -> 512.
//   * producers: coalesced neighbor-index load (1 LDG + shfl instead of 10
//     broadcast LDGs), all 4 rows' feature loads interleaved (MLP ~44).
// ============================================================================

static constexpr int BLK_M   = 32;
static constexpr int K_DIM   = 256;
static constexpr int H_OUT   = 128;
static constexpr int S_NEIGH = 10;
static constexpr int ROW_ELEM = 264;                  // 256 + 8 pad (bf16)
static constexpr int ROW_B    = ROW_ELEM * 2;         // 528 bytes
static constexpr int W_BYTES  = H_OUT * ROW_B;        // 67584 per half
static constexpr int A_HALF   = BLK_M * ROW_B;        // 16896 (hi or lo)
static constexpr int A_STAGE  = 2 * A_HALF;           // 33792 (hi+lo)
static constexpr int NSTAGE   = 2;

// smem layout
static constexpr int SM_WHI   = 0;
static constexpr int SM_WLO   = SM_WHI + W_BYTES;     // 67584
static constexpr int SM_A     = SM_WLO + W_BYTES;     // 135168
static constexpr int SM_BAR   = SM_A + NSTAGE * A_STAGE;  // 202752
static constexpr int SM_TOTAL = SM_BAR + 64;          // 202816

__device__ __align__(16) unsigned char g_whi[W_BYTES];
__device__ __align__(16) unsigned char g_wlo[W_BYTES];

// ---------------- helpers ----------------
__device__ __forceinline__ uint32_t smem_u32(const void* p) {
    uint32_t a;
    asm("{ .reg .u64 t; cvta.to.shared.u64 t, %1; cvt.u32.u64 %0, t; }"
        : "=r"(a) : "l"(p));
    return a;
}

__device__ __forceinline__ void split_bf16(float x, __nv_bfloat16& h, __nv_bfloat16& l) {
    h = __float2bfloat16(x);
    l = __float2bfloat16(x - __bfloat162float(h));
}

__device__ __forceinline__ void ldsm_x4(uint32_t (&d)[4], uint32_t addr) {
    asm volatile("ldmatrix.sync.aligned.m8n8.x4.shared.b16 {%0,%1,%2,%3}, [%4];"
                 : "=r"(d[0]), "=r"(d[1]), "=r"(d[2]), "=r"(d[3]) : "r"(addr));
}

__device__ __forceinline__ void mma_bf16(float (&c)[4], const uint32_t (&a)[4],
                                         uint32_t b0, uint32_t b1) {
    asm volatile(
        "mma.sync.aligned.m16n8k16.row.col.f32.bf16.bf16.f32 "
        "{%0,%1,%2,%3}, {%4,%5,%6,%7}, {%8,%9}, {%0,%1,%2,%3};"
        : "+f"(c[0]), "+f"(c[1]), "+f"(c[2]), "+f"(c[3])
        : "r"(a[0]), "r"(a[1]), "r"(a[2]), "r"(a[3]), "r"(b0), "r"(b1));
}

#define MBARRIER_INIT(mbar, count) \
    asm volatile("mbarrier.init.shared.b64 [%0], %1;" \
                 :: "r"((uint32_t)(mbar)), "r"((uint32_t)(count)) : "memory")

#define MBARRIER_ARRIVE(mbar) \
    asm volatile("mbarrier.arrive.shared.b64 _, [%0];" \
                 :: "r"((uint32_t)(mbar)) : "memory")

#define MBARRIER_WAIT_PARITY(mbar, parity) do {                                  \
    uint32_t _m = (uint32_t)(mbar); uint32_t _p = (uint32_t)(parity);            \
    asm volatile(                                                                \
        "{\n\t.reg .pred P1;\n\t"                                                \
        "WAIT_LOOP_%=:\n\t"                                                      \
        "mbarrier.try_wait.parity.shared.b64 P1, [%0], %1;\n\t"                  \
        "@P1 bra.uni WAIT_DONE_%=;\n\t"                                          \
        "bra.uni WAIT_LOOP_%=;\n\t"                                              \
        "WAIT_DONE_%=:\n\t}"                                                     \
        :: "r"(_m), "r"(_p) : "memory");                                         \
} while (0)

#define FULL_BAR(sb, s)  ((sb) + SM_BAR + (s) * 16)
#define EMPTY_BAR(sb, s) ((sb) + SM_BAR + (s) * 16 + 8)

// ---------------- weight prep ----------------
__global__ void sage_prep_weight(const float* __restrict__ w) {
    int i = blockIdx.x * blockDim.x + threadIdx.x;
    if (i >= K_DIM * H_OUT) return;
    int k = i >> 7;
    int n = i & 127;
    __nv_bfloat16 h, l;
    split_bf16(w[i], h, l);
    uint32_t off = (uint32_t)n * ROW_B + (uint32_t)k * 2;   // [n][k] K-major
    *reinterpret_cast<__nv_bfloat16*>(g_whi + off) = h;
    *reinterpret_cast<__nv_bfloat16*>(g_wlo + off) = l;
}

// ---------------- fused persistent warp-specialized kernel -------------------
__global__ __launch_bounds__(512, 1)
void sage_main(const int* __restrict__ nodes,
               const int* __restrict__ neigh,
               const float* __restrict__ feat,
               float* __restrict__ out,
               int B, int ntiles) {
    extern __shared__ __align__(16) char smem[];
    const uint32_t sb   = smem_u32(smem);
    const int tid  = threadIdx.x;
    const int wid  = tid >> 5;
    const int lane = tid & 31;

    if (tid == 0) {
        #pragma unroll
        for (int s = 0; s < NSTAGE; s++) {
            MBARRIER_INIT(FULL_BAR(sb, s), 256);   // 8 producer warps arrive
            MBARRIER_INIT(EMPTY_BAR(sb, s), 128);  // 4 consumer warps (group) arrive
        }
    }

    // copy both weight halves into smem once
    {
        const uint4* s0 = reinterpret_cast<const uint4*>(g_whi);
        const uint4* s1 = reinterpret_cast<const uint4*>(g_wlo);
        uint4* d0 = reinterpret_cast<uint4*>(smem + SM_WHI);
        uint4* d1 = reinterpret_cast<uint4*>(smem + SM_WLO);
        for (int i = tid; i < W_BYTES / 16; i += 512) { d0[i] = s0[i]; d1[i] = s1[i]; }
    }
    __syncthreads();

    if (wid < 8) {
        // ============ PRODUCERS: gather + mean + bf16 split ============
        const float4* feat4 = reinterpret_cast<const float4*>(feat);
        int stage = 0, phase = 1;   // first empty-wait passes immediately

        for (int tile = blockIdx.x; tile < ntiles; tile += gridDim.x) {
            const int base = tile * BLK_M;
            MBARRIER_WAIT_PARITY(EMPTY_BAR(sb, stage), phase);
            const uint32_t aHi = sb + SM_A + stage * A_STAGE;
            const uint32_t aLo = aHi + A_HALF;

            // --- prefetch indices for all 4 rows (coalesced neigh load) ---
            int srcr[4], idxv[4], selfi[4];
            #pragma unroll
            for (int i = 0; i < 4; i++) {
                const int grow = base + wid * 4 + i;
                srcr[i] = (grow < B) ? grow : 0;
                selfi[i] = __ldg(nodes + srcr[i]);
                idxv[i] = (lane < S_NEIGH)
                          ? __ldg(neigh + (size_t)srcr[i] * S_NEIGH + lane) : 0;
            }

            // --- all feature loads interleaved across rows (MLP ~44) ---
            float4 sv[4];
            float4 acc[4];
            #pragma unroll
            for (int i = 0; i < 4; i++) {
                sv[i] = __ldg(feat4 + (size_t)selfi[i] * 32 + lane);
                acc[i] = make_float4(0.f, 0.f, 0.f, 0.f);
            }
            #pragma unroll
            for (int s = 0; s < S_NEIGH; s++) {
                #pragma unroll
                for (int i = 0; i < 4; i++) {
                    const int ni = __shfl_sync(0xffffffffu, idxv[i], s);
                    const float4 v = __ldg(feat4 + (size_t)ni * 32 + lane);
                    acc[i].x += v.x; acc[i].y += v.y;
                    acc[i].z += v.z; acc[i].w += v.w;
                }
            }

            // --- split + store ---
            #pragma unroll
            for (int i = 0; i < 4; i++) {
                const int r = wid * 4 + i;
                const float4 mv = make_float4(acc[i].x * 0.1f, acc[i].y * 0.1f,
                                              acc[i].z * 0.1f, acc[i].w * 0.1f);
                #pragma unroll
                for (int part = 0; part < 2; part++) {
                    const float4 v = part ? mv : sv[i];
                    const int kcol = part * 128 + 4 * lane;
                    __nv_bfloat16 h0,h1,h2,h3,l0,l1,l2,l3;
                    split_bf16(v.x, h0, l0); split_bf16(v.y, h1, l1);
                    split_bf16(v.z, h2, l2); split_bf16(v.w, h3, l3);
                    __nv_bfloat162 hp0{h0,h1}, hp1{h2,h3}, lp0{l0,l1}, lp1{l2,l3};
                    const uint32_t hx = *reinterpret_cast<uint32_t*>(&hp0);
                    const uint32_t hy = *reinterpret_cast<uint32_t*>(&hp1);
                    const uint32_t lx = *reinterpret_cast<uint32_t*>(&lp0);
                    const uint32_t ly = *reinterpret_cast<uint32_t*>(&lp1);
                    const uint32_t off = (uint32_t)r * ROW_B + (uint32_t)kcol * 2;
                    asm volatile("st.shared.v2.b32 [%0], {%1, %2};"
                                 :: "r"(aHi + off), "r"(hx), "r"(hy) : "memory");
                    asm volatile("st.shared.v2.b32 [%0], {%1, %2};"
                                 :: "r"(aLo + off), "r"(lx), "r"(ly) : "memory");
                }
            }

            __threadfence_block();
            MBARRIER_ARRIVE(FULL_BAR(sb, stage));
            if (++stage == NSTAGE) { stage = 0; phase ^= 1; }
        }
    } else {
        // ============ CONSUMERS: 2 groups x 4 warps, 32x32 warp tiles ============
        const int cw    = wid - 8;          // 0..7
        const int group = cw >> 2;          // 0: even local tiles, 1: odd
        const int nc    = (cw & 3) * 32;    // 0,32,64,96
        const uint32_t sWhi = sb + SM_WHI;
        const uint32_t sWlo = sb + SM_WLO;

        const uint32_t a_row  = (uint32_t)(lane & 15);
        const uint32_t a_coff = (uint32_t)(((lane >> 4) << 3) * 2);
        const uint32_t b_row  = (uint32_t)(nc + (lane & 7) + ((lane & 16) >> 1));
        const uint32_t b_coff = (uint32_t)((lane & 8) * 2);
        const uint32_t aoff0  = a_row * ROW_B + a_coff;
        const uint32_t boff0  = b_row * ROW_B + b_coff;

        const uint32_t aHi = sb + SM_A + group * A_STAGE;   // stage == group
        const uint32_t aLo = aHi + A_HALF;
        int phase = 0;

        for (int t = group; ; t += 2) {
            const long tile = (long)blockIdx.x + (long)t * gridDim.x;
            if (tile >= ntiles) break;
            const int base = (int)tile * BLK_M;

            MBARRIER_WAIT_PARITY(FULL_BAR(sb, group), phase);
            phase ^= 1;

            float acc[2][4][4];
            #pragma unroll
            for (int m = 0; m < 2; m++)
                #pragma unroll
                for (int n = 0; n < 4; n++)
                    #pragma unroll
                    for (int j = 0; j < 4; j++) acc[m][n][j] = 0.f;

            #pragma unroll
            for (int k = 0; k < K_DIM / 16; k++) {
                const uint32_t kb = (uint32_t)(k * 32);

                uint32_t ah0[4], ah1[4], al0[4], al1[4];
                ldsm_x4(ah0, aHi + aoff0 + kb);
                ldsm_x4(ah1, aHi + aoff0 + kb + 16 * ROW_B);
                ldsm_x4(al0, aLo + aoff0 + kb);
                ldsm_x4(al1, aLo + aoff0 + kb + 16 * ROW_B);

                uint32_t bh0[4], bh1[4], bl0[4], bl1[4];
                ldsm_x4(bh0, sWhi + boff0 + kb);
                ldsm_x4(bh1, sWhi + boff0 + kb + 16 * ROW_B);
                ldsm_x4(bl0, sWlo + boff0 + kb);
                ldsm_x4(bl1, sWlo + boff0 + kb + 16 * ROW_B);

                // Ah * Wh
                mma_bf16(acc[0][0], ah0, bh0[0], bh0[1]);
                mma_bf16(acc[0][1], ah0, bh0[2], bh0[3]);
                mma_bf16(acc[0][2], ah0, bh1[0], bh1[1]);
                mma_bf16(acc[0][3], ah0, bh1[2], bh1[3]);
                mma_bf16(acc[1][0], ah1, bh0[0], bh0[1]);
                mma_bf16(acc[1][1], ah1, bh0[2], bh0[3]);
                mma_bf16(acc[1][2], ah1, bh1[0], bh1[1]);
                mma_bf16(acc[1][3], ah1, bh1[2], bh1[3]);
                // Al * Wh
                mma_bf16(acc[0][0], al0, bh0[0], bh0[1]);
                mma_bf16(acc[0][1], al0, bh0[2], bh0[3]);
                mma_bf16(acc[0][2], al0, bh1[0], bh1[1]);
                mma_bf16(acc[0][3], al0, bh1[2], bh1[3]);
                mma_bf16(acc[1][0], al1, bh0[0], bh0[1]);
                mma_bf16(acc[1][1], al1, bh0[2], bh0[3]);
                mma_bf16(acc[1][2], al1, bh1[0], bh1[1]);
                mma_bf16(acc[1][3], al1, bh1[2], bh1[3]);
                // Ah * Wl
                mma_bf16(acc[0][0], ah0, bl0[0], bl0[1]);
                mma_bf16(acc[0][1], ah0, bl0[2], bl0[3]);
                mma_bf16(acc[0][2], ah0, bl1[0], bl1[1]);
                mma_bf16(acc[0][3], ah0, bl1[2], bl1[3]);
                mma_bf16(acc[1][0], ah1, bl0[0], bl0[1]);
                mma_bf16(acc[1][1], ah1, bl0[2], bl0[3]);
                mma_bf16(acc[1][2], ah1, bl1[0], bl1[1]);
                mma_bf16(acc[1][3], ah1, bl1[2], bl1[3]);
            }

            MBARRIER_ARRIVE(EMPTY_BAR(sb, group));

            // epilogue from registers (stage already released)
            #pragma unroll
            for (int mi = 0; mi < 2; mi++) {
                const int r0 = base + mi * 16 + (lane >> 2);
                #pragma unroll
                for (int nt = 0; nt < 4; nt++) {
                    const int c = nc + nt * 8 + 2 * (lane & 3);
                    if (r0 < B) {
                        float2 v;
                        v.x = fmaxf(acc[mi][nt][0], 0.f);
                        v.y = fmaxf(acc[mi][nt][1], 0.f);
                        *reinterpret_cast<float2*>(out + (size_t)r0 * H_OUT + c) = v;
                    }
                    if (r0 + 8 < B) {
                        float2 v;
                        v.x = fmaxf(acc[mi][nt][2], 0.f);
                        v.y = fmaxf(acc[mi][nt][3], 0.f);
                        *reinterpret_cast<float2*>(out + (size_t)(r0 + 8) * H_OUT + c) = v;
                    }
                }
            }
        }
    }
}

// ---------------- launch ------------------------------------------------------
extern "C" void kernel_launch(void* const* d_in, const int* in_sizes, int n_in,
                              void* d_out, int out_size) {
    const int*   nodes  = (const int*)d_in[0];
    const int*   neigh  = (const int*)d_in[1];
    const float* feat   = (const float*)d_in[2];
    const float* weight = (const float*)d_in[3];
    float*       out    = (float*)d_out;
    const int B = in_sizes[0];
    const int ntiles = (B + BLK_M - 1) / BLK_M;

    sage_prep_weight<<<(K_DIM * H_OUT + 255) / 256, 256>>>(weight);

    cudaFuncSetAttribute(sage_main, cudaFuncAttributeMaxDynamicSharedMemorySize, SM_TOTAL);
    const int grid = (ntiles < 148) ? ntiles : 148;
    sage_main<<<grid, 512, SM_TOTAL>>>(nodes, neigh, feat, out, B, ntiles);
}

// round 9
// speedup vs baseline: 1.5867x; 1.0308x over previous
#include <cuda_runtime.h>
#include <cuda_bf16.h>
#include <cstdint>

// ============================================================================
// GraphSAGE fused layer — sm_103 baseline-PTX, warp-specialized pipeline (R7).
//
//   out = relu(concat(feature[nodes], mean(feature[neigh_idx],1)) @ W)
//   B=50000, S=10, D=128, H=128, K=256.
//
// R7 deltas vs R6 (from ncu: issue 19.8%, L1 51% => producer-latency bound):
//   * producer software pipeline: next tile's indices prefetched during the
//     current tile's feature loads; empty-wait moved AFTER the gather (only
//     the STS needs the stage), so load latency overlaps consumer drain
//   * 3-stage A ring (absorbs jitter); fits by replacing 528B padding with an
//     XOR swizzle (512B pitch, 16B-chunk ^ (row&7)) — conflict-free for
//     ldmatrix 8-row reads and producer 8B stores
//   * consumers: 2 groups x 4 warps, group g consumes tiles t==g (mod 2),
//     stage = t mod 3, FULL-bar parity constant per (group,stage): (s&1)^g
// ============================================================================

static constexpr int BLK_M   = 32;
static constexpr int K_DIM   = 256;
static constexpr int H_OUT   = 128;
static constexpr int S_NEIGH = 10;
static constexpr int ROW_B   = 512;                   // 256 bf16, no pad (swizzled)
static constexpr int W_BYTES = H_OUT * ROW_B;         // 65536 per half
static constexpr int A_HALF  = BLK_M * ROW_B;         // 16384 (hi or lo)
static constexpr int A_STAGE = 2 * A_HALF;            // 32768
static constexpr int NSTAGE  = 3;

// smem layout
static constexpr int SM_WHI   = 0;
static constexpr int SM_WLO   = SM_WHI + W_BYTES;         // 65536
static constexpr int SM_A     = SM_WLO + W_BYTES;         // 131072
static constexpr int SM_BAR   = SM_A + NSTAGE * A_STAGE;  // 229376
static constexpr int SM_TOTAL = SM_BAR + 64;              // 229440 (< 227KB max)

__device__ __align__(16) unsigned char g_whi[W_BYTES];
__device__ __align__(16) unsigned char g_wlo[W_BYTES];

// ---------------- helpers ----------------
__device__ __forceinline__ uint32_t smem_u32(const void* p) {
    uint32_t a;
    asm("{ .reg .u64 t; cvta.to.shared.u64 t, %1; cvt.u32.u64 %0, t; }"
        : "=r"(a) : "l"(p));
    return a;
}

__device__ __forceinline__ void split_bf16(float x, __nv_bfloat16& h, __nv_bfloat16& l) {
    h = __float2bfloat16(x);
    l = __float2bfloat16(x - __bfloat162float(h));
}

// swizzled byte offset for element (row, kcol) in a 512B-pitch bf16 tile:
// 16B chunk index XORed with row%8
__host__ __device__ __forceinline__ uint32_t sw_off(int row, int kcol) {
    uint32_t byte  = (uint32_t)kcol * 2u;
    uint32_t chunk = (byte >> 4) ^ ((uint32_t)row & 7u);
    return (uint32_t)row * ROW_B + (chunk << 4) + (byte & 15u);
}

__device__ __forceinline__ void ldsm_x4(uint32_t (&d)[4], uint32_t addr) {
    asm volatile("ldmatrix.sync.aligned.m8n8.x4.shared.b16 {%0,%1,%2,%3}, [%4];"
                 : "=r"(d[0]), "=r"(d[1]), "=r"(d[2]), "=r"(d[3]) : "r"(addr));
}

__device__ __forceinline__ void mma_bf16(float (&c)[4], const uint32_t (&a)[4],
                                         uint32_t b0, uint32_t b1) {
    asm volatile(
        "mma.sync.aligned.m16n8k16.row.col.f32.bf16.bf16.f32 "
        "{%0,%1,%2,%3}, {%4,%5,%6,%7}, {%8,%9}, {%0,%1,%2,%3};"
        : "+f"(c[0]), "+f"(c[1]), "+f"(c[2]), "+f"(c[3])
        : "r"(a[0]), "r"(a[1]), "r"(a[2]), "r"(a[3]), "r"(b0), "r"(b1));
}

#define MBARRIER_INIT(mbar, count) \
    asm volatile("mbarrier.init.shared.b64 [%0], %1;" \
                 :: "r"((uint32_t)(mbar)), "r"((uint32_t)(count)) : "memory")

#define MBARRIER_ARRIVE(mbar) \
    asm volatile("mbarrier.arrive.shared.b64 _, [%0];" \
                 :: "r"((uint32_t)(mbar)) : "memory")

#define MBARRIER_WAIT_PARITY(mbar, parity) do {                                  \
    uint32_t _m = (uint32_t)(mbar); uint32_t _p = (uint32_t)(parity);            \
    asm volatile(                                                                \
        "{\n\t.reg .pred P1;\n\t"                                                \
        "WAIT_LOOP_%=:\n\t"                                                      \
        "mbarrier.try_wait.parity.shared.b64 P1, [%0], %1;\n\t"                  \
        "@P1 bra.uni WAIT_DONE_%=;\n\t"                                          \
        "bra.uni WAIT_LOOP_%=;\n\t"                                              \
        "WAIT_DONE_%=:\n\t}"                                                     \
        :: "r"(_m), "r"(_p) : "memory");                                         \
} while (0)

#define FULL_BAR(sb, s)  ((sb) + SM_BAR + (s) * 16)
#define EMPTY_BAR(sb, s) ((sb) + SM_BAR + (s) * 16 + 8)

// ---------------- weight prep: transpose + hi/lo split + swizzle ------------
__global__ void sage_prep_weight(const float* __restrict__ w) {
    int i = blockIdx.x * blockDim.x + threadIdx.x;
    if (i >= K_DIM * H_OUT) return;
    int k = i >> 7;        // weight row (0..255)
    int n = i & 127;       // weight col (0..127)
    __nv_bfloat16 h, l;
    split_bf16(w[i], h, l);
    uint32_t off = sw_off(n, k);                        // [n][k] K-major, swizzled
    *reinterpret_cast<__nv_bfloat16*>(g_whi + off) = h;
    *reinterpret_cast<__nv_bfloat16*>(g_wlo + off) = l;
}

// ---------------- fused persistent warp-specialized kernel -------------------
__global__ __launch_bounds__(512, 1)
void sage_main(const int* __restrict__ nodes,
               const int* __restrict__ neigh,
               const float* __restrict__ feat,
               float* __restrict__ out,
               int B, int ntiles) {
    extern __shared__ __align__(16) char smem[];
    const uint32_t sb   = smem_u32(smem);
    const int tid  = threadIdx.x;
    const int wid  = tid >> 5;
    const int lane = tid & 31;

    if (tid == 0) {
        #pragma unroll
        for (int s = 0; s < NSTAGE; s++) {
            MBARRIER_INIT(FULL_BAR(sb, s), 256);   // 8 producer warps arrive
            MBARRIER_INIT(EMPTY_BAR(sb, s), 128);  // 4 consumer warps arrive
        }
    }

    // copy both weight halves into smem once (swizzle preserved by linear copy)
    {
        const uint4* s0 = reinterpret_cast<const uint4*>(g_whi);
        const uint4* s1 = reinterpret_cast<const uint4*>(g_wlo);
        uint4* d0 = reinterpret_cast<uint4*>(smem + SM_WHI);
        uint4* d1 = reinterpret_cast<uint4*>(smem + SM_WLO);
        for (int i = tid; i < W_BYTES / 16; i += 512) { d0[i] = s0[i]; d1[i] = s1[i]; }
    }
    __syncthreads();

    if (wid < 8) {
        // ============ PRODUCERS: pipelined gather + mean + bf16 split ============
        const float4* feat4 = reinterpret_cast<const float4*>(feat);
        int stage = 0;
        int ph0 = 1, ph1 = 1, ph2 = 1;   // per-stage empty parities (first pass free)

        // prologue: indices for first tile
        int selfi[4], idxv[4];
        {
            const int base = blockIdx.x * BLK_M;
            #pragma unroll
            for (int i = 0; i < 4; i++) {
                const int grow = base + wid * 4 + i;
                const int src = (grow < B) ? grow : 0;
                selfi[i] = __ldg(nodes + src);
                idxv[i] = (lane < S_NEIGH)
                          ? __ldg(neigh + (size_t)src * S_NEIGH + lane) : 0;
            }
        }

        for (int tile = blockIdx.x; tile < ntiles; tile += gridDim.x) {
            // --- feature loads for current tile (indices already resident) ---
            float4 sv[4], acc[4];
            #pragma unroll
            for (int i = 0; i < 4; i++) {
                sv[i] = __ldg(feat4 + (size_t)selfi[i] * 32 + lane);
                acc[i] = make_float4(0.f, 0.f, 0.f, 0.f);
            }

            // --- prefetch next tile's indices (latency hidden behind features) ---
            int nselfi[4], nidxv[4];
            {
                const long nt = (long)tile + gridDim.x;
                const int nbase = (nt < ntiles) ? (int)nt * BLK_M : 0;
                #pragma unroll
                for (int i = 0; i < 4; i++) {
                    const int grow = nbase + wid * 4 + i;
                    const int src = (grow < B) ? grow : 0;
                    nselfi[i] = __ldg(nodes + src);
                    nidxv[i] = (lane < S_NEIGH)
                               ? __ldg(neigh + (size_t)src * S_NEIGH + lane) : 0;
                }
            }

            #pragma unroll
            for (int s = 0; s < S_NEIGH; s++) {
                #pragma unroll
                for (int i = 0; i < 4; i++) {
                    const int ni = __shfl_sync(0xffffffffu, idxv[i], s);
                    const float4 v = __ldg(feat4 + (size_t)ni * 32 + lane);
                    acc[i].x += v.x; acc[i].y += v.y;
                    acc[i].z += v.z; acc[i].w += v.w;
                }
            }

            // --- only now claim the stage buffer ---
            const int p = (stage == 0) ? ph0 : (stage == 1) ? ph1 : ph2;
            MBARRIER_WAIT_PARITY(EMPTY_BAR(sb, stage), p);
            if (stage == 0) ph0 ^= 1; else if (stage == 1) ph1 ^= 1; else ph2 ^= 1;

            const uint32_t aHi = sb + SM_A + stage * A_STAGE;
            const uint32_t aLo = aHi + A_HALF;

            #pragma unroll
            for (int i = 0; i < 4; i++) {
                const int r = wid * 4 + i;
                const float4 mv = make_float4(acc[i].x * 0.1f, acc[i].y * 0.1f,
                                              acc[i].z * 0.1f, acc[i].w * 0.1f);
                #pragma unroll
                for (int part = 0; part < 2; part++) {
                    const float4 v = part ? mv : sv[i];
                    const int kcol = part * 128 + 4 * lane;
                    __nv_bfloat16 h0,h1,h2,h3,l0,l1,l2,l3;
                    split_bf16(v.x, h0, l0); split_bf16(v.y, h1, l1);
                    split_bf16(v.z, h2, l2); split_bf16(v.w, h3, l3);
                    __nv_bfloat162 hp0{h0,h1}, hp1{h2,h3}, lp0{l0,l1}, lp1{l2,l3};
                    const uint32_t hx = *reinterpret_cast<uint32_t*>(&hp0);
                    const uint32_t hy = *reinterpret_cast<uint32_t*>(&hp1);
                    const uint32_t lx = *reinterpret_cast<uint32_t*>(&lp0);
                    const uint32_t ly = *reinterpret_cast<uint32_t*>(&lp1);
                    const uint32_t off = sw_off(r, kcol);
                    asm volatile("st.shared.v2.b32 [%0], {%1, %2};"
                                 :: "r"(aHi + off), "r"(hx), "r"(hy) : "memory");
                    asm volatile("st.shared.v2.b32 [%0], {%1, %2};"
                                 :: "r"(aLo + off), "r"(lx), "r"(ly) : "memory");
                }
            }

            __threadfence_block();
            MBARRIER_ARRIVE(FULL_BAR(sb, stage));
            stage = (stage == NSTAGE - 1) ? 0 : stage + 1;

            #pragma unroll
            for (int i = 0; i < 4; i++) { selfi[i] = nselfi[i]; idxv[i] = nidxv[i]; }
        }
    } else {
        // ============ CONSUMERS: 2 groups x 4 warps, 32x32 warp tiles ============
        const int cw    = wid - 8;          // 0..7
        const int group = cw >> 2;          // group g consumes tiles t==g (mod 2)
        const int nc    = (cw & 3) * 32;    // 0,32,64,96
        const uint32_t sWhi = sb + SM_WHI;
        const uint32_t sWlo = sb + SM_WLO;

        // ldmatrix address components (swizzled): addr = base + row*512 +
        //   ((chunk ^ (row&7)) << 4), chunk = 2k + sel
        const uint32_t a_row = (uint32_t)(lane & 15);
        const uint32_t a_sel = (uint32_t)(lane >> 4);          // 0/1
        const uint32_t b_row = (uint32_t)(nc + (lane & 7) + ((lane & 16) >> 1));
        const uint32_t b_sel = (uint32_t)((lane >> 3) & 1);    // 0/1
        const uint32_t a_x   = a_row & 7u;
        const uint32_t b_x   = b_row & 7u;
        const uint32_t aRowB = a_row * ROW_B;
        const uint32_t bRowB = b_row * ROW_B;

        int stage = group;                  // t=group -> stage = group

        for (int t = group; ; t += 2) {
            const long tile = (long)blockIdx.x + (long)t * gridDim.x;
            if (tile >= ntiles) break;
            const int base = (int)tile * BLK_M;

            MBARRIER_WAIT_PARITY(FULL_BAR(sb, stage), (stage & 1) ^ group);

            const uint32_t aHi = sb + SM_A + stage * A_STAGE;
            const uint32_t aLo = aHi + A_HALF;

            float acc[2][4][4];
            #pragma unroll
            for (int m = 0; m < 2; m++)
                #pragma unroll
                for (int n = 0; n < 4; n++)
                    #pragma unroll
                    for (int j = 0; j < 4; j++) acc[m][n][j] = 0.f;

            #pragma unroll
            for (int k = 0; k < K_DIM / 16; k++) {
                const uint32_t ac = (((2u * k + a_sel) ^ a_x) << 4);
                const uint32_t bc = (((2u * k + b_sel) ^ b_x) << 4);
                const uint32_t aoff = aRowB + ac;
                const uint32_t boff = bRowB + bc;

                uint32_t ah0[4], ah1[4], al0[4], al1[4];
                ldsm_x4(ah0, aHi + aoff);
                ldsm_x4(ah1, aHi + aoff + 16 * ROW_B);
                ldsm_x4(al0, aLo + aoff);
                ldsm_x4(al1, aLo + aoff + 16 * ROW_B);

                uint32_t bh0[4], bh1[4], bl0[4], bl1[4];
                ldsm_x4(bh0, sWhi + boff);
                ldsm_x4(bh1, sWhi + boff + 16 * ROW_B);
                ldsm_x4(bl0, sWlo + boff);
                ldsm_x4(bl1, sWlo + boff + 16 * ROW_B);

                // Ah * Wh
                mma_bf16(acc[0][0], ah0, bh0[0], bh0[1]);
                mma_bf16(acc[0][1], ah0, bh0[2], bh0[3]);
                mma_bf16(acc[0][2], ah0, bh1[0], bh1[1]);
                mma_bf16(acc[0][3], ah0, bh1[2], bh1[3]);
                mma_bf16(acc[1][0], ah1, bh0[0], bh0[1]);
                mma_bf16(acc[1][1], ah1, bh0[2], bh0[3]);
                mma_bf16(acc[1][2], ah1, bh1[0], bh1[1]);
                mma_bf16(acc[1][3], ah1, bh1[2], bh1[3]);
                // Al * Wh
                mma_bf16(acc[0][0], al0, bh0[0], bh0[1]);
                mma_bf16(acc[0][1], al0, bh0[2], bh0[3]);
                mma_bf16(acc[0][2], al0, bh1[0], bh1[1]);
                mma_bf16(acc[0][3], al0, bh1[2], bh1[3]);
                mma_bf16(acc[1][0], al1, bh0[0], bh0[1]);
                mma_bf16(acc[1][1], al1, bh0[2], bh0[3]);
                mma_bf16(acc[1][2], al1, bh1[0], bh1[1]);
                mma_bf16(acc[1][3], al1, bh1[2], bh1[3]);
                // Ah * Wl
                mma_bf16(acc[0][0], ah0, bl0[0], bl0[1]);
                mma_bf16(acc[0][1], ah0, bl0[2], bl0[3]);
                mma_bf16(acc[0][2], ah0, bl1[0], bl1[1]);
                mma_bf16(acc[0][3], ah0, bl1[2], bl1[3]);
                mma_bf16(acc[1][0], ah1, bl0[0], bl0[1]);
                mma_bf16(acc[1][1], ah1, bl0[2], bl0[3]);
                mma_bf16(acc[1][2], ah1, bl1[0], bl1[1]);
                mma_bf16(acc[1][3], ah1, bl1[2], bl1[3]);
            }

            MBARRIER_ARRIVE(EMPTY_BAR(sb, stage));

            // epilogue from registers (stage already released)
            #pragma unroll
            for (int mi = 0; mi < 2; mi++) {
                const int r0 = base + mi * 16 + (lane >> 2);
                #pragma unroll
                for (int nt = 0; nt < 4; nt++) {
                    const int c = nc + nt * 8 + 2 * (lane & 3);
                    if (r0 < B) {
                        float2 v;
                        v.x = fmaxf(acc[mi][nt][0], 0.f);
                        v.y = fmaxf(acc[mi][nt][1], 0.f);
                        *reinterpret_cast<float2*>(out + (size_t)r0 * H_OUT + c) = v;
                    }
                    if (r0 + 8 < B) {
                        float2 v;
                        v.x = fmaxf(acc[mi][nt][2], 0.f);
                        v.y = fmaxf(acc[mi][nt][3], 0.f);
                        *reinterpret_cast<float2*>(out + (size_t)(r0 + 8) * H_OUT + c) = v;
                    }
                }
            }

            stage += 2; if (stage >= NSTAGE) stage -= NSTAGE;
        }
    }
}

// ---------------- launch ------------------------------------------------------
extern "C" void kernel_launch(void* const* d_in, const int* in_sizes, int n_in,
                              void* d_out, int out_size) {
    const int*   nodes  = (const int*)d_in[0];
    const int*   neigh  = (const int*)d_in[1];
    const float* feat   = (const float*)d_in[2];
    const float* weight = (const float*)d_in[3];
    float*       out    = (float*)d_out;
    const int B = in_sizes[0];
    const int ntiles = (B + BLK_M - 1) / BLK_M;

    sage_prep_weight<<<(K_DIM * H_OUT + 255) / 256, 256>>>(weight);

    cudaFuncSetAttribute(sage_main, cudaFuncAttributeMaxDynamicSharedMemorySize, SM_TOTAL);
    const int grid = (ntiles < 148) ? ntiles : 148;
    sage_main<<<grid, 512, SM_TOTAL>>>(nodes, neigh, feat, out, B, ntiles);
}

// round 10
// speedup vs baseline: 1.7328x; 1.0921x over previous
#include <cuda_runtime.h>
#include <cuda_fp16.h>
#include <cstdint>

// ============================================================================
// GraphSAGE fused layer — sm_103 baseline-PTX, warp-specialized pipeline (R8).
//
//   out = relu(concat(feature[nodes], mean(feature[neigh_idx],1)) @ W)
//   B=50000, S=10, D=128, H=128, K=256.
//
// R8 delta vs R7: SINGLE fp16 product replaces 3-product bf16 hi/lo split.
//   fp16 mma products are exact with fp32 accumulate; only input rounding
//   (2^-11) contributes => aggregate rel err ~4e-4 < 1e-3 threshold.
//   - HMMA per tile /3, consumer LDSM /3, producer STS /2
//   - A stage 16KB -> 4-stage ring; regs free up for scheduling
// Structure kept from R7: 8 producer warps (gather+mean, idx prefetch,
// empty-wait after gather), 8 consumer warps in 2 groups x 4 (32x32 tiles),
// XOR-swizzled 512B-pitch smem, persistent grid=148.
// ============================================================================

static constexpr int BLK_M   = 32;
static constexpr int K_DIM   = 256;
static constexpr int H_OUT   = 128;
static constexpr int S_NEIGH = 10;
static constexpr int ROW_B   = 512;                   // 256 fp16, swizzled
static constexpr int W_BYTES = H_OUT * ROW_B;         // 65536
static constexpr int A_STAGE = BLK_M * ROW_B;         // 16384
static constexpr int NSTAGE  = 4;

// smem layout
static constexpr int SM_W     = 0;
static constexpr int SM_A     = SM_W + W_BYTES;           // 65536
static constexpr int SM_BAR   = SM_A + NSTAGE * A_STAGE;  // 131072
static constexpr int SM_TOTAL = SM_BAR + 80;

__device__ __align__(16) unsigned char g_wh[W_BYTES];

// ---------------- helpers ----------------
__device__ __forceinline__ uint32_t smem_u32(const void* p) {
    uint32_t a;
    asm("{ .reg .u64 t; cvta.to.shared.u64 t, %1; cvt.u32.u64 %0, t; }"
        : "=r"(a) : "l"(p));
    return a;
}

// swizzled byte offset for element (row, kcol) in a 512B-pitch fp16 tile:
// 16B chunk index XORed with row%8
__host__ __device__ __forceinline__ uint32_t sw_off(int row, int kcol) {
    uint32_t byte  = (uint32_t)kcol * 2u;
    uint32_t chunk = (byte >> 4) ^ ((uint32_t)row & 7u);
    return (uint32_t)row * ROW_B + (chunk << 4) + (byte & 15u);
}

__device__ __forceinline__ void ldsm_x4(uint32_t (&d)[4], uint32_t addr) {
    asm volatile("ldmatrix.sync.aligned.m8n8.x4.shared.b16 {%0,%1,%2,%3}, [%4];"
                 : "=r"(d[0]), "=r"(d[1]), "=r"(d[2]), "=r"(d[3]) : "r"(addr));
}

__device__ __forceinline__ void mma_f16(float (&c)[4], const uint32_t (&a)[4],
                                        uint32_t b0, uint32_t b1) {
    asm volatile(
        "mma.sync.aligned.m16n8k16.row.col.f32.f16.f16.f32 "
        "{%0,%1,%2,%3}, {%4,%5,%6,%7}, {%8,%9}, {%0,%1,%2,%3};"
        : "+f"(c[0]), "+f"(c[1]), "+f"(c[2]), "+f"(c[3])
        : "r"(a[0]), "r"(a[1]), "r"(a[2]), "r"(a[3]), "r"(b0), "r"(b1));
}

#define MBARRIER_INIT(mbar, count) \
    asm volatile("mbarrier.init.shared.b64 [%0], %1;" \
                 :: "r"((uint32_t)(mbar)), "r"((uint32_t)(count)) : "memory")

#define MBARRIER_ARRIVE(mbar) \
    asm volatile("mbarrier.arrive.shared.b64 _, [%0];" \
                 :: "r"((uint32_t)(mbar)) : "memory")

#define MBARRIER_WAIT_PARITY(mbar, parity) do {                                  \
    uint32_t _m = (uint32_t)(mbar); uint32_t _p = (uint32_t)(parity);            \
    asm volatile(                                                                \
        "{\n\t.reg .pred P1;\n\t"                                                \
        "WAIT_LOOP_%=:\n\t"                                                      \
        "mbarrier.try_wait.parity.shared.b64 P1, [%0], %1;\n\t"                  \
        "@P1 bra.uni WAIT_DONE_%=;\n\t"                                          \
        "bra.uni WAIT_LOOP_%=;\n\t"                                              \
        "WAIT_DONE_%=:\n\t}"                                                     \
        :: "r"(_m), "r"(_p) : "memory");                                         \
} while (0)

#define FULL_BAR(sb, s)  ((sb) + SM_BAR + (s) * 16)
#define EMPTY_BAR(sb, s) ((sb) + SM_BAR + (s) * 16 + 8)

// ---------------- weight prep: transpose + fp16 + swizzle --------------------
__global__ void sage_prep_weight(const float* __restrict__ w) {
    int i = blockIdx.x * blockDim.x + threadIdx.x;
    if (i >= K_DIM * H_OUT) return;
    int k = i >> 7;        // weight row (0..255)
    int n = i & 127;       // weight col (0..127)
    *reinterpret_cast<__half*>(g_wh + sw_off(n, k)) = __float2half_rn(w[i]);
}

// ---------------- fused persistent warp-specialized kernel -------------------
__global__ __launch_bounds__(512, 1)
void sage_main(const int* __restrict__ nodes,
               const int* __restrict__ neigh,
               const float* __restrict__ feat,
               float* __restrict__ out,
               int B, int ntiles) {
    extern __shared__ __align__(16) char smem[];
    const uint32_t sb   = smem_u32(smem);
    const int tid  = threadIdx.x;
    const int wid  = tid >> 5;
    const int lane = tid & 31;

    if (tid == 0) {
        #pragma unroll
        for (int s = 0; s < NSTAGE; s++) {
            MBARRIER_INIT(FULL_BAR(sb, s), 256);   // 8 producer warps arrive
            MBARRIER_INIT(EMPTY_BAR(sb, s), 128);  // 4 consumer warps arrive
        }
    }

    // copy weight into smem once (swizzle preserved by linear copy)
    {
        const uint4* s0 = reinterpret_cast<const uint4*>(g_wh);
        uint4* d0 = reinterpret_cast<uint4*>(smem + SM_W);
        for (int i = tid; i < W_BYTES / 16; i += 512) d0[i] = s0[i];
    }
    __syncthreads();

    if (wid < 8) {
        // ============ PRODUCERS: pipelined gather + mean + fp16 pack ============
        const float4* feat4 = reinterpret_cast<const float4*>(feat);
        int stage = 0;
        uint32_t eph = 0xFu;   // per-stage empty parities (first pass free)

        // prologue: indices for first tile
        int selfi[4], idxv[4];
        {
            const int base = blockIdx.x * BLK_M;
            #pragma unroll
            for (int i = 0; i < 4; i++) {
                const int grow = base + wid * 4 + i;
                const int src = (grow < B) ? grow : 0;
                selfi[i] = __ldg(nodes + src);
                idxv[i] = (lane < S_NEIGH)
                          ? __ldg(neigh + (size_t)src * S_NEIGH + lane) : 0;
            }
        }

        for (int tile = blockIdx.x; tile < ntiles; tile += gridDim.x) {
            // --- feature loads for current tile (indices already resident) ---
            float4 sv[4], acc[4];
            #pragma unroll
            for (int i = 0; i < 4; i++) {
                sv[i] = __ldg(feat4 + (size_t)selfi[i] * 32 + lane);
                acc[i] = make_float4(0.f, 0.f, 0.f, 0.f);
            }

            // --- prefetch next tile's indices (hidden behind feature loads) ---
            int nselfi[4], nidxv[4];
            {
                const long nt = (long)tile + gridDim.x;
                const int nbase = (nt < ntiles) ? (int)nt * BLK_M : 0;
                #pragma unroll
                for (int i = 0; i < 4; i++) {
                    const int grow = nbase + wid * 4 + i;
                    const int src = (grow < B) ? grow : 0;
                    nselfi[i] = __ldg(nodes + src);
                    nidxv[i] = (lane < S_NEIGH)
                               ? __ldg(neigh + (size_t)src * S_NEIGH + lane) : 0;
                }
            }

            #pragma unroll
            for (int s = 0; s < S_NEIGH; s++) {
                #pragma unroll
                for (int i = 0; i < 4; i++) {
                    const int ni = __shfl_sync(0xffffffffu, idxv[i], s);
                    const float4 v = __ldg(feat4 + (size_t)ni * 32 + lane);
                    acc[i].x += v.x; acc[i].y += v.y;
                    acc[i].z += v.z; acc[i].w += v.w;
                }
            }

            // --- claim the stage buffer only now ---
            MBARRIER_WAIT_PARITY(EMPTY_BAR(sb, stage), (eph >> stage) & 1u);
            eph ^= (1u << stage);

            const uint32_t aT = sb + SM_A + stage * A_STAGE;

            #pragma unroll
            for (int i = 0; i < 4; i++) {
                const int r = wid * 4 + i;
                const float4 mv = make_float4(acc[i].x * 0.1f, acc[i].y * 0.1f,
                                              acc[i].z * 0.1f, acc[i].w * 0.1f);
                #pragma unroll
                for (int part = 0; part < 2; part++) {
                    const float4 v = part ? mv : sv[i];
                    const int kcol = part * 128 + 4 * lane;
                    __half2 p0 = __floats2half2_rn(v.x, v.y);
                    __half2 p1 = __floats2half2_rn(v.z, v.w);
                    const uint32_t r0 = *reinterpret_cast<uint32_t*>(&p0);
                    const uint32_t r1 = *reinterpret_cast<uint32_t*>(&p1);
                    asm volatile("st.shared.v2.b32 [%0], {%1, %2};"
                                 :: "r"(aT + sw_off(r, kcol)), "r"(r0), "r"(r1)
                                 : "memory");
                }
            }

            __threadfence_block();
            MBARRIER_ARRIVE(FULL_BAR(sb, stage));
            stage = (stage + 1) & (NSTAGE - 1);

            #pragma unroll
            for (int i = 0; i < 4; i++) { selfi[i] = nselfi[i]; idxv[i] = nidxv[i]; }
        }
    } else {
        // ============ CONSUMERS: 2 groups x 4 warps, 32x32 warp tiles ============
        const int cw    = wid - 8;          // 0..7
        const int group = cw >> 2;          // group g consumes tiles t==g (mod 2)
        const int nc    = (cw & 3) * 32;    // 0,32,64,96
        const uint32_t sW = sb + SM_W;

        const uint32_t a_row = (uint32_t)(lane & 15);
        const uint32_t a_sel = (uint32_t)(lane >> 4);          // 0/1
        const uint32_t b_row = (uint32_t)(nc + (lane & 7) + ((lane & 16) >> 1));
        const uint32_t b_sel = (uint32_t)((lane >> 3) & 1);    // 0/1
        const uint32_t a_x   = a_row & 7u;
        const uint32_t b_x   = b_row & 7u;
        const uint32_t aRowB = a_row * ROW_B;
        const uint32_t bRowB = b_row * ROW_B;

        // group g's stages: {g, g+2}, visited alternately; per-stage phases
        int stage = group;
        int phA = 0, phB = 0;      // phA for stage 'group', phB for 'group+2'
        int which = 0;             // 0 -> stage group, 1 -> stage group+2

        for (int t = group; ; t += 2) {
            const long tile = (long)blockIdx.x + (long)t * gridDim.x;
            if (tile >= ntiles) break;
            const int base = (int)tile * BLK_M;

            const int ph = which ? phB : phA;
            MBARRIER_WAIT_PARITY(FULL_BAR(sb, stage), ph);

            const uint32_t aT = sb + SM_A + stage * A_STAGE;

            float acc[2][4][4];
            #pragma unroll
            for (int m = 0; m < 2; m++)
                #pragma unroll
                for (int n = 0; n < 4; n++)
                    #pragma unroll
                    for (int j = 0; j < 4; j++) acc[m][n][j] = 0.f;

            #pragma unroll
            for (int k = 0; k < K_DIM / 16; k++) {
                const uint32_t ac = (((2u * k + a_sel) ^ a_x) << 4);
                const uint32_t bc = (((2u * k + b_sel) ^ b_x) << 4);

                uint32_t a0[4], a1[4];
                ldsm_x4(a0, aT + aRowB + ac);
                ldsm_x4(a1, aT + aRowB + ac + 16 * ROW_B);

                uint32_t b0[4], b1[4];
                ldsm_x4(b0, sW + bRowB + bc);
                ldsm_x4(b1, sW + bRowB + bc + 16 * ROW_B);

                mma_f16(acc[0][0], a0, b0[0], b0[1]);
                mma_f16(acc[0][1], a0, b0[2], b0[3]);
                mma_f16(acc[0][2], a0, b1[0], b1[1]);
                mma_f16(acc[0][3], a0, b1[2], b1[3]);
                mma_f16(acc[1][0], a1, b0[0], b0[1]);
                mma_f16(acc[1][1], a1, b0[2], b0[3]);
                mma_f16(acc[1][2], a1, b1[0], b1[1]);
                mma_f16(acc[1][3], a1, b1[2], b1[3]);
            }

            MBARRIER_ARRIVE(EMPTY_BAR(sb, stage));
            if (which) phB ^= 1; else phA ^= 1;
            which ^= 1;
            stage = group + 2 * which;   // alternate {group, group+2}

            // epilogue from registers (stage already released)
            #pragma unroll
            for (int mi = 0; mi < 2; mi++) {
                const int r0 = base + mi * 16 + (lane >> 2);
                #pragma unroll
                for (int nt = 0; nt < 4; nt++) {
                    const int c = nc + nt * 8 + 2 * (lane & 3);
                    if (r0 < B) {
                        float2 v;
                        v.x = fmaxf(acc[mi][nt][0], 0.f);
                        v.y = fmaxf(acc[mi][nt][1], 0.f);
                        *reinterpret_cast<float2*>(out + (size_t)r0 * H_OUT + c) = v;
                    }
                    if (r0 + 8 < B) {
                        float2 v;
                        v.x = fmaxf(acc[mi][nt][2], 0.f);
                        v.y = fmaxf(acc[mi][nt][3], 0.f);
                        *reinterpret_cast<float2*>(out + (size_t)(r0 + 8) * H_OUT + c) = v;
                    }
                }
            }
        }
    }
}

// ---------------- launch ------------------------------------------------------
extern "C" void kernel_launch(void* const* d_in, const int* in_sizes, int n_in,
                              void* d_out, int out_size) {
    const int*   nodes  = (const int*)d_in[0];
    const int*   neigh  = (const int*)d_in[1];
    const float* feat   = (const float*)d_in[2];
    const float* weight = (const float*)d_in[3];
    float*       out    = (float*)d_out;
    const int B = in_sizes[0];
    const int ntiles = (B + BLK_M - 1) / BLK_M;

    sage_prep_weight<<<(K_DIM * H_OUT + 255) / 256, 256>>>(weight);

    cudaFuncSetAttribute(sage_main, cudaFuncAttributeMaxDynamicSharedMemorySize, SM_TOTAL);
    const int grid = (ntiles < 148) ? ntiles : 148;
    sage_main<<<grid, 512, SM_TOTAL>>>(nodes, neigh, feat, out, B, ntiles);
}